// round 5
// baseline (speedup 1.0000x reference)
#include <cuda_runtime.h>
#include <math.h>

#define QQ   12240
#define NB   2
#define NQ   (NB*QQ)       // 24480
#define KD   256

// ---- scratch (static device globals; allocation is forbidden) ----
__device__ float g_vproj [NQ * 256];
__device__ float g_off   [NQ * 256];
__device__ float g_attn  [NQ * 128];
__device__ float g_outpre[NQ * 256];

// ---------------------------------------------------------------------------
// TF32 tensor-core GEMM: C[M,N] = A[M,256] @ W[256,N] + bias[N]
// BM=128, BN=128, BK=16, 256 threads (8 warps, 64x32 warp tiles),
// double-buffered smem, mma.sync.m16n8k8.tf32, fp32 accumulate.
// ---------------------------------------------------------------------------
#define BM 128
#define BN 128
#define BK 16
#define SA 136   // smem row stride (words): LDS banks (8k+m)%32 all distinct

__device__ __forceinline__ unsigned f2tf(float x) {
    unsigned r; asm("cvt.rna.tf32.f32 %0, %1;" : "=r"(r) : "f"(x)); return r;
}

__device__ __forceinline__ void mma_tf32(float* c, const unsigned* a, const unsigned* b) {
    asm volatile(
        "mma.sync.aligned.m16n8k8.row.col.f32.tf32.tf32.f32 "
        "{%0,%1,%2,%3}, {%4,%5,%6,%7}, {%8,%9}, {%0,%1,%2,%3};"
        : "+f"(c[0]), "+f"(c[1]), "+f"(c[2]), "+f"(c[3])
        : "r"(a[0]), "r"(a[1]), "r"(a[2]), "r"(a[3]), "r"(b[0]), "r"(b[1]));
}

__global__ __launch_bounds__(256) void gemm_tf32_kernel(
    const float* __restrict__ A,
    const float* __restrict__ W,
    const float* __restrict__ bias,
    float* __restrict__ C,
    int M, int N)
{
    __shared__ float As[2][BK][SA];   // As[buf][k][m]  (tf32 bit patterns)
    __shared__ float Bs[2][BK][SA];   // Bs[buf][k][n]

    const int tid  = threadIdx.x;
    const int lane = tid & 31;
    const int warp = tid >> 5;
    const int bm = blockIdx.x * BM;
    const int bn = blockIdx.y * BN;
    const int wm = (warp >> 2) << 6;   // 0 or 64
    const int wn = (warp & 3) << 5;    // 0,32,64,96

    const int ar = tid >> 1;             // 0..127
    const int ac = (tid & 1) << 3;       // 0 or 8
    const bool aval = (bm + ar) < M;
    const float* Ap = A + (size_t)(bm + ar) * KD + ac;

    const int br = tid >> 4;             // 0..15
    const int bc = (tid & 15) << 3;      // 0..120
    const float* Wp = W + (size_t)br * N + bn + bc;

    const int fr = lane >> 2;            // fragment row group 0..7
    const int fk = lane & 3;             // fragment k 0..3

    float acc[4][4][4];
    #pragma unroll
    for (int i = 0; i < 4; i++)
        #pragma unroll
        for (int j = 0; j < 4; j++)
            #pragma unroll
            for (int c = 0; c < 4; c++) acc[i][j][c] = 0.f;

    float4 av0, av1, bv0, bv1;
    if (aval) { av0 = *(const float4*)Ap; av1 = *(const float4*)(Ap + 4); }
    else      { av0 = make_float4(0,0,0,0); av1 = av0; }
    bv0 = *(const float4*)Wp;
    bv1 = *(const float4*)(Wp + 4);

    As[0][ac+0][ar] = __uint_as_float(f2tf(av0.x));
    As[0][ac+1][ar] = __uint_as_float(f2tf(av0.y));
    As[0][ac+2][ar] = __uint_as_float(f2tf(av0.z));
    As[0][ac+3][ar] = __uint_as_float(f2tf(av0.w));
    As[0][ac+4][ar] = __uint_as_float(f2tf(av1.x));
    As[0][ac+5][ar] = __uint_as_float(f2tf(av1.y));
    As[0][ac+6][ar] = __uint_as_float(f2tf(av1.z));
    As[0][ac+7][ar] = __uint_as_float(f2tf(av1.w));
    {
        float4 t0 = make_float4(__uint_as_float(f2tf(bv0.x)), __uint_as_float(f2tf(bv0.y)),
                                __uint_as_float(f2tf(bv0.z)), __uint_as_float(f2tf(bv0.w)));
        float4 t1 = make_float4(__uint_as_float(f2tf(bv1.x)), __uint_as_float(f2tf(bv1.y)),
                                __uint_as_float(f2tf(bv1.z)), __uint_as_float(f2tf(bv1.w)));
        *(float4*)&Bs[0][br][bc]     = t0;
        *(float4*)&Bs[0][br][bc + 4] = t1;
    }
    __syncthreads();

    const int NIT = KD / BK;   // 16
    for (int iter = 0; iter < NIT; iter++) {
        const int buf = iter & 1;

        if (iter + 1 < NIT) {
            const float* Ap2 = Ap + (iter + 1) * BK;
            if (aval) { av0 = *(const float4*)Ap2; av1 = *(const float4*)(Ap2 + 4); }
            const float* Wp2 = Wp + (size_t)(iter + 1) * BK * N;
            bv0 = *(const float4*)Wp2;
            bv1 = *(const float4*)(Wp2 + 4);
        }

        #pragma unroll
        for (int kk = 0; kk < BK; kk += 8) {
            unsigned af[4][4], bf[4][2];
            const int k0 = kk + fk;
            #pragma unroll
            for (int mt = 0; mt < 4; mt++) {
                const int m = wm + (mt << 4) + fr;
                af[mt][0] = __float_as_uint(As[buf][k0    ][m    ]);
                af[mt][1] = __float_as_uint(As[buf][k0    ][m + 8]);
                af[mt][2] = __float_as_uint(As[buf][k0 + 4][m    ]);
                af[mt][3] = __float_as_uint(As[buf][k0 + 4][m + 8]);
            }
            #pragma unroll
            for (int nt = 0; nt < 4; nt++) {
                const int nn = wn + (nt << 3) + fr;
                bf[nt][0] = __float_as_uint(Bs[buf][k0    ][nn]);
                bf[nt][1] = __float_as_uint(Bs[buf][k0 + 4][nn]);
            }
            #pragma unroll
            for (int mt = 0; mt < 4; mt++)
                #pragma unroll
                for (int nt = 0; nt < 4; nt++)
                    mma_tf32(acc[mt][nt], af[mt], bf[nt]);
        }

        if (iter + 1 < NIT) {
            const int nb = buf ^ 1;
            As[nb][ac+0][ar] = __uint_as_float(f2tf(av0.x));
            As[nb][ac+1][ar] = __uint_as_float(f2tf(av0.y));
            As[nb][ac+2][ar] = __uint_as_float(f2tf(av0.z));
            As[nb][ac+3][ar] = __uint_as_float(f2tf(av0.w));
            As[nb][ac+4][ar] = __uint_as_float(f2tf(av1.x));
            As[nb][ac+5][ar] = __uint_as_float(f2tf(av1.y));
            As[nb][ac+6][ar] = __uint_as_float(f2tf(av1.z));
            As[nb][ac+7][ar] = __uint_as_float(f2tf(av1.w));
            float4 t0 = make_float4(__uint_as_float(f2tf(bv0.x)), __uint_as_float(f2tf(bv0.y)),
                                    __uint_as_float(f2tf(bv0.z)), __uint_as_float(f2tf(bv0.w)));
            float4 t1 = make_float4(__uint_as_float(f2tf(bv1.x)), __uint_as_float(f2tf(bv1.y)),
                                    __uint_as_float(f2tf(bv1.z)), __uint_as_float(f2tf(bv1.w)));
            *(float4*)&Bs[nb][br][bc]     = t0;
            *(float4*)&Bs[nb][br][bc + 4] = t1;
            __syncthreads();
        }
    }

    #pragma unroll
    for (int nt = 0; nt < 4; nt++) {
        const int cc = bn + wn + (nt << 3) + ((lane & 3) << 1);
        const float2 bv = *(const float2*)(bias + cc);
        #pragma unroll
        for (int mt = 0; mt < 4; mt++) {
            const int r0 = bm + wm + (mt << 4) + (lane >> 2);
            if (r0 < M) {
                float2 o = make_float2(acc[mt][nt][0] + bv.x, acc[mt][nt][1] + bv.y);
                *(float2*)(C + (size_t)r0 * N + cc) = o;
            }
            if (r0 + 8 < M) {
                float2 o = make_float2(acc[mt][nt][2] + bv.x, acc[mt][nt][3] + bv.y);
                *(float2*)(C + (size_t)(r0 + 8) * N + cc) = o;
            }
        }
    }
}

// ---------------------------------------------------------------------------
// Deformable sampling. One warp per (n, q, head); lane == channel (CH=32).
// Phase A: lane j<16 computes point j's 4 pre-masked weights (x softmax) and
//          4 pre-scaled clamped indices; writes them to smem (2x STS.128).
// Phase B: per point, 2 broadcast LDS.128 + 4 coalesced LDG + 4 FMA.
// ---------------------------------------------------------------------------
__global__ __launch_bounds__(256) void sample_kernel(
    const float* __restrict__ pref,
    float* __restrict__ outpre)
{
    __shared__ float sW[8][16][4];   // per warp, per point: W00,W10,W01,W11
    __shared__ int   sI[8][16][4];   // i00,i10,i01,i11 (pre-scaled by 256)

    const unsigned FULL = 0xffffffffu;
    const int lane = threadIdx.x & 31;
    const int wip  = threadIdx.x >> 5;
    const int warp = (blockIdx.x << 3) + wip;
    const int h    = warp & 7;
    const int nq   = warp >> 3;
    const int n    = (nq >= QQ) ? 1 : 0;

    const int jj = lane & 15;
    const int l  = jj >> 2;
    const int Wl = 96 >> l;
    const float fw = (float)Wl;
    const int sb = (l == 0) ? 0 : (l == 1) ? 9216 : (l == 2) ? 11520 : 12096;

    // ---- softmax over this head's 16 logits (dup across warp halves) ----
    float logit = g_attn[nq * 128 + h * 16 + jj];
    float mx = logit;
    #pragma unroll
    for (int o = 8; o >= 1; o >>= 1)
        mx = fmaxf(mx, __shfl_xor_sync(FULL, mx, o));
    float e = __expf(logit - mx);
    float s = e;
    #pragma unroll
    for (int o = 8; o >= 1; o >>= 1)
        s += __shfl_xor_sync(FULL, s, o);
    const float aw = e / s;

    // ---- point jj: coords / masked weights / clamped indices ----
    const float2 o2 = ((const float2*)(g_off + nq * 256 + h * 32))[jj];
    const float2 pr = ((const float2*)(pref + nq * 8))[l];
    const float x = fmaf(pr.x, fw, o2.x) - 0.5f;   // == (p + off/W)*W - 0.5
    const float y = fmaf(pr.y, fw, o2.y) - 0.5f;
    const float x0f = floorf(x), y0f = floorf(y);
    const float dx = x - x0f, dy = y - y0f;
    const int x0 = (int)x0f, y0 = (int)y0f;
    const int x1 = x0 + 1,   y1 = y0 + 1;
    const bool vx0 = (unsigned)x0 < (unsigned)Wl;
    const bool vx1 = (unsigned)x1 < (unsigned)Wl;
    const bool vy0 = (unsigned)y0 < (unsigned)Wl;
    const bool vy1 = (unsigned)y1 < (unsigned)Wl;
    const int x0c = min(max(x0, 0), Wl - 1);
    const int x1c = min(max(x1, 0), Wl - 1);
    const int y0c = min(max(y0, 0), Wl - 1);
    const int y1c = min(max(y1, 0), Wl - 1);
    const float ex = 1.f - dx, ey = 1.f - dy;
    const float u0 = aw * ex, u1 = aw * dx;

    if (lane < 16) {
        float4 wv;
        wv.x = (vx0 & vy0) ? u0 * ey : 0.f;
        wv.y = (vx1 & vy0) ? u1 * ey : 0.f;
        wv.z = (vx0 & vy1) ? u0 * dy : 0.f;
        wv.w = (vx1 & vy1) ? u1 * dy : 0.f;
        const int r0 = sb + y0c * Wl;
        const int r1 = sb + y1c * Wl;
        int4 iv;
        iv.x = (r0 + x0c) << 8;
        iv.y = (r0 + x1c) << 8;
        iv.z = (r1 + x0c) << 8;
        iv.w = (r1 + x1c) << 8;
        *(float4*)sW[wip][jj] = wv;
        *(int4*)  sI[wip][jj] = iv;
    }
    __syncwarp();

    // ---- gather & accumulate ----
    const float* vp = g_vproj + (size_t)n * (QQ * 256) + h * 32 + lane;
    float a0 = 0.f, a1 = 0.f, a2 = 0.f, a3 = 0.f;
    #pragma unroll
    for (int j = 0; j < 16; j++) {
        const float4 wv = *(const float4*)sW[wip][j];   // broadcast LDS.128
        const int4   iv = *(const int4*)  sI[wip][j];   // broadcast LDS.128
        a0 = fmaf(wv.x, __ldg(vp + iv.x), a0);
        a1 = fmaf(wv.y, __ldg(vp + iv.y), a1);
        a2 = fmaf(wv.z, __ldg(vp + iv.z), a2);
        a3 = fmaf(wv.w, __ldg(vp + iv.w), a3);
    }
    outpre[nq * 256 + h * 32 + lane] = (a0 + a1) + (a2 + a3);
}

// ---------------------------------------------------------------------------
extern "C" void kernel_launch(void* const* d_in, const int* in_sizes, int n_in,
                              void* d_out, int out_size)
{
    (void)in_sizes; (void)n_in; (void)out_size;
    const float* q      = (const float*)d_in[0];
    const float* p      = (const float*)d_in[1];
    const float* v      = (const float*)d_in[2];
    const float* W_off  = (const float*)d_in[3];
    const float* b_off  = (const float*)d_in[4];
    const float* W_attn = (const float*)d_in[5];
    const float* b_attn = (const float*)d_in[6];
    const float* W_in   = (const float*)d_in[7];
    const float* b_in   = (const float*)d_in[8];
    const float* W_out  = (const float*)d_in[9];
    const float* b_out  = (const float*)d_in[10];
    float* out = (float*)d_out;

    static float *vproj = nullptr, *offb = nullptr, *attnb = nullptr, *outpre = nullptr;
    if (!vproj) {
        cudaGetSymbolAddress((void**)&vproj,  g_vproj);
        cudaGetSymbolAddress((void**)&offb,   g_off);
        cudaGetSymbolAddress((void**)&attnb,  g_attn);
        cudaGetSymbolAddress((void**)&outpre, g_outpre);
    }

    dim3 blk(256);
    dim3 g256((NQ + BM - 1) / BM, 256 / BN);   // (192, 2)
    dim3 g128((NQ + BM - 1) / BM, 128 / BN);   // (192, 1)

    gemm_tf32_kernel<<<g256, blk>>>(v,      W_in,   b_in,   vproj,  NQ, 256);
    gemm_tf32_kernel<<<g256, blk>>>(q,      W_off,  b_off,  offb,   NQ, 256);
    gemm_tf32_kernel<<<g128, blk>>>(q,      W_attn, b_attn, attnb,  NQ, 128);
    sample_kernel<<<NQ, 256>>>(p, outpre);
    gemm_tf32_kernel<<<g256, blk>>>(outpre, W_out,  b_out,  out,    NQ, 256);
}

// round 6
// speedup vs baseline: 1.0184x; 1.0184x over previous
#include <cuda_runtime.h>
#include <math.h>

#define QQ   12240
#define NB   2
#define NQ   (NB*QQ)       // 24480
#define KD   256

// ---- scratch (static device globals; allocation is forbidden) ----
__device__ float g_vproj [NQ * 256];
__device__ float g_off   [NQ * 256];
__device__ float g_attn  [NQ * 128];
__device__ float g_outpre[NQ * 256];

// ---------------------------------------------------------------------------
// TF32 tensor-core GEMM: C[M,N] = A[M,256] @ W[256,N] + bias[N]
// BM=128, BN=128, BK=16, 256 threads (8 warps, 64x32 warp tiles),
// double-buffered smem, mma.sync.m16n8k8.tf32, fp32 accumulate.
// ---------------------------------------------------------------------------
#define BM 128
#define BN 128
#define BK 16
#define SA 136   // smem row stride (words): LDS banks (8k+m)%32 all distinct

__device__ __forceinline__ unsigned f2tf(float x) {
    unsigned r; asm("cvt.rna.tf32.f32 %0, %1;" : "=r"(r) : "f"(x)); return r;
}

__device__ __forceinline__ void mma_tf32(float* c, const unsigned* a, const unsigned* b) {
    asm volatile(
        "mma.sync.aligned.m16n8k8.row.col.f32.tf32.tf32.f32 "
        "{%0,%1,%2,%3}, {%4,%5,%6,%7}, {%8,%9}, {%0,%1,%2,%3};"
        : "+f"(c[0]), "+f"(c[1]), "+f"(c[2]), "+f"(c[3])
        : "r"(a[0]), "r"(a[1]), "r"(a[2]), "r"(a[3]), "r"(b[0]), "r"(b[1]));
}

__global__ __launch_bounds__(256) void gemm_tf32_kernel(
    const float* __restrict__ A,
    const float* __restrict__ W,
    const float* __restrict__ bias,
    float* __restrict__ C,
    int M, int N)
{
    __shared__ float As[2][BK][SA];   // As[buf][k][m]  (tf32 bit patterns)
    __shared__ float Bs[2][BK][SA];   // Bs[buf][k][n]

    const int tid  = threadIdx.x;
    const int lane = tid & 31;
    const int warp = tid >> 5;
    const int bm = blockIdx.x * BM;
    const int bn = blockIdx.y * BN;
    const int wm = (warp >> 2) << 6;   // 0 or 64
    const int wn = (warp & 3) << 5;    // 0,32,64,96

    const int ar = tid >> 1;             // 0..127
    const int ac = (tid & 1) << 3;       // 0 or 8
    const bool aval = (bm + ar) < M;
    const float* Ap = A + (size_t)(bm + ar) * KD + ac;

    const int br = tid >> 4;             // 0..15
    const int bc = (tid & 15) << 3;      // 0..120
    const float* Wp = W + (size_t)br * N + bn + bc;

    const int fr = lane >> 2;            // fragment row group 0..7
    const int fk = lane & 3;             // fragment k 0..3

    float acc[4][4][4];
    #pragma unroll
    for (int i = 0; i < 4; i++)
        #pragma unroll
        for (int j = 0; j < 4; j++)
            #pragma unroll
            for (int c = 0; c < 4; c++) acc[i][j][c] = 0.f;

    float4 av0, av1, bv0, bv1;
    if (aval) { av0 = *(const float4*)Ap; av1 = *(const float4*)(Ap + 4); }
    else      { av0 = make_float4(0,0,0,0); av1 = av0; }
    bv0 = *(const float4*)Wp;
    bv1 = *(const float4*)(Wp + 4);

    As[0][ac+0][ar] = __uint_as_float(f2tf(av0.x));
    As[0][ac+1][ar] = __uint_as_float(f2tf(av0.y));
    As[0][ac+2][ar] = __uint_as_float(f2tf(av0.z));
    As[0][ac+3][ar] = __uint_as_float(f2tf(av0.w));
    As[0][ac+4][ar] = __uint_as_float(f2tf(av1.x));
    As[0][ac+5][ar] = __uint_as_float(f2tf(av1.y));
    As[0][ac+6][ar] = __uint_as_float(f2tf(av1.z));
    As[0][ac+7][ar] = __uint_as_float(f2tf(av1.w));
    {
        float4 t0 = make_float4(__uint_as_float(f2tf(bv0.x)), __uint_as_float(f2tf(bv0.y)),
                                __uint_as_float(f2tf(bv0.z)), __uint_as_float(f2tf(bv0.w)));
        float4 t1 = make_float4(__uint_as_float(f2tf(bv1.x)), __uint_as_float(f2tf(bv1.y)),
                                __uint_as_float(f2tf(bv1.z)), __uint_as_float(f2tf(bv1.w)));
        *(float4*)&Bs[0][br][bc]     = t0;
        *(float4*)&Bs[0][br][bc + 4] = t1;
    }
    __syncthreads();

    const int NIT = KD / BK;   // 16
    for (int iter = 0; iter < NIT; iter++) {
        const int buf = iter & 1;

        if (iter + 1 < NIT) {
            const float* Ap2 = Ap + (iter + 1) * BK;
            if (aval) { av0 = *(const float4*)Ap2; av1 = *(const float4*)(Ap2 + 4); }
            const float* Wp2 = Wp + (size_t)(iter + 1) * BK * N;
            bv0 = *(const float4*)Wp2;
            bv1 = *(const float4*)(Wp2 + 4);
        }

        #pragma unroll
        for (int kk = 0; kk < BK; kk += 8) {
            unsigned af[4][4], bf[4][2];
            const int k0 = kk + fk;
            #pragma unroll
            for (int mt = 0; mt < 4; mt++) {
                const int m = wm + (mt << 4) + fr;
                af[mt][0] = __float_as_uint(As[buf][k0    ][m    ]);
                af[mt][1] = __float_as_uint(As[buf][k0    ][m + 8]);
                af[mt][2] = __float_as_uint(As[buf][k0 + 4][m    ]);
                af[mt][3] = __float_as_uint(As[buf][k0 + 4][m + 8]);
            }
            #pragma unroll
            for (int nt = 0; nt < 4; nt++) {
                const int nn = wn + (nt << 3) + fr;
                bf[nt][0] = __float_as_uint(Bs[buf][k0    ][nn]);
                bf[nt][1] = __float_as_uint(Bs[buf][k0 + 4][nn]);
            }
            #pragma unroll
            for (int mt = 0; mt < 4; mt++)
                #pragma unroll
                for (int nt = 0; nt < 4; nt++)
                    mma_tf32(acc[mt][nt], af[mt], bf[nt]);
        }

        if (iter + 1 < NIT) {
            const int nb = buf ^ 1;
            As[nb][ac+0][ar] = __uint_as_float(f2tf(av0.x));
            As[nb][ac+1][ar] = __uint_as_float(f2tf(av0.y));
            As[nb][ac+2][ar] = __uint_as_float(f2tf(av0.z));
            As[nb][ac+3][ar] = __uint_as_float(f2tf(av0.w));
            As[nb][ac+4][ar] = __uint_as_float(f2tf(av1.x));
            As[nb][ac+5][ar] = __uint_as_float(f2tf(av1.y));
            As[nb][ac+6][ar] = __uint_as_float(f2tf(av1.z));
            As[nb][ac+7][ar] = __uint_as_float(f2tf(av1.w));
            float4 t0 = make_float4(__uint_as_float(f2tf(bv0.x)), __uint_as_float(f2tf(bv0.y)),
                                    __uint_as_float(f2tf(bv0.z)), __uint_as_float(f2tf(bv0.w)));
            float4 t1 = make_float4(__uint_as_float(f2tf(bv1.x)), __uint_as_float(f2tf(bv1.y)),
                                    __uint_as_float(f2tf(bv1.z)), __uint_as_float(f2tf(bv1.w)));
            *(float4*)&Bs[nb][br][bc]     = t0;
            *(float4*)&Bs[nb][br][bc + 4] = t1;
            __syncthreads();
        }
    }

    #pragma unroll
    for (int nt = 0; nt < 4; nt++) {
        const int cc = bn + wn + (nt << 3) + ((lane & 3) << 1);
        const float2 bv = *(const float2*)(bias + cc);
        #pragma unroll
        for (int mt = 0; mt < 4; mt++) {
            const int r0 = bm + wm + (mt << 4) + (lane >> 2);
            if (r0 < M) {
                float2 o = make_float2(acc[mt][nt][0] + bv.x, acc[mt][nt][1] + bv.y);
                *(float2*)(C + (size_t)r0 * N + cc) = o;
            }
            if (r0 + 8 < M) {
                float2 o = make_float2(acc[mt][nt][2] + bv.x, acc[mt][nt][3] + bv.y);
                *(float2*)(C + (size_t)(r0 + 8) * N + cc) = o;
            }
        }
    }
}

// ---------------------------------------------------------------------------
// Deformable sampling. One warp per (n, q, head); lane == channel (CH=32).
// Phase A: lane j<16 computes point j's 4 pre-masked weights (x softmax) and
//          4 pre-scaled clamped indices; writes them to smem (2x STS.128).
// Phase B: per point, 2 broadcast LDS.128 + 4 coalesced LDG + 4 FMA.
// ---------------------------------------------------------------------------
__global__ __launch_bounds__(256) void sample_kernel(
    const float* __restrict__ pref,
    float* __restrict__ outpre)
{
    __shared__ float sW[8][16][4];   // per warp, per point: W00,W10,W01,W11
    __shared__ int   sI[8][16][4];   // i00,i10,i01,i11 (pre-scaled by 256)

    const unsigned FULL = 0xffffffffu;
    const int lane = threadIdx.x & 31;
    const int wip  = threadIdx.x >> 5;
    const int warp = (blockIdx.x << 3) + wip;
    const int h    = warp & 7;
    const int nq   = warp >> 3;
    const int n    = (nq >= QQ) ? 1 : 0;

    const int jj = lane & 15;
    const int l  = jj >> 2;
    const int Wl = 96 >> l;
    const float fw = (float)Wl;
    const int sb = (l == 0) ? 0 : (l == 1) ? 9216 : (l == 2) ? 11520 : 12096;

    // ---- softmax over this head's 16 logits (dup across warp halves) ----
    float logit = g_attn[nq * 128 + h * 16 + jj];
    float mx = logit;
    #pragma unroll
    for (int o = 8; o >= 1; o >>= 1)
        mx = fmaxf(mx, __shfl_xor_sync(FULL, mx, o));
    float e = __expf(logit - mx);
    float s = e;
    #pragma unroll
    for (int o = 8; o >= 1; o >>= 1)
        s += __shfl_xor_sync(FULL, s, o);
    const float aw = e / s;

    // ---- point jj: coords / masked weights / clamped indices ----
    const float2 o2 = ((const float2*)(g_off + nq * 256 + h * 32))[jj];
    const float2 pr = ((const float2*)(pref + nq * 8))[l];
    const float x = fmaf(pr.x, fw, o2.x) - 0.5f;   // == (p + off/W)*W - 0.5
    const float y = fmaf(pr.y, fw, o2.y) - 0.5f;
    const float x0f = floorf(x), y0f = floorf(y);
    const float dx = x - x0f, dy = y - y0f;
    const int x0 = (int)x0f, y0 = (int)y0f;
    const int x1 = x0 + 1,   y1 = y0 + 1;
    const bool vx0 = (unsigned)x0 < (unsigned)Wl;
    const bool vx1 = (unsigned)x1 < (unsigned)Wl;
    const bool vy0 = (unsigned)y0 < (unsigned)Wl;
    const bool vy1 = (unsigned)y1 < (unsigned)Wl;
    const int x0c = min(max(x0, 0), Wl - 1);
    const int x1c = min(max(x1, 0), Wl - 1);
    const int y0c = min(max(y0, 0), Wl - 1);
    const int y1c = min(max(y1, 0), Wl - 1);
    const float ex = 1.f - dx, ey = 1.f - dy;
    const float u0 = aw * ex, u1 = aw * dx;

    if (lane < 16) {
        float4 wv;
        wv.x = (vx0 & vy0) ? u0 * ey : 0.f;
        wv.y = (vx1 & vy0) ? u1 * ey : 0.f;
        wv.z = (vx0 & vy1) ? u0 * dy : 0.f;
        wv.w = (vx1 & vy1) ? u1 * dy : 0.f;
        const int r0 = sb + y0c * Wl;
        const int r1 = sb + y1c * Wl;
        int4 iv;
        iv.x = (r0 + x0c) << 8;
        iv.y = (r0 + x1c) << 8;
        iv.z = (r1 + x0c) << 8;
        iv.w = (r1 + x1c) << 8;
        *(float4*)sW[wip][jj] = wv;
        *(int4*)  sI[wip][jj] = iv;
    }
    __syncwarp();

    // ---- gather & accumulate ----
    const float* vp = g_vproj + (size_t)n * (QQ * 256) + h * 32 + lane;
    float a0 = 0.f, a1 = 0.f, a2 = 0.f, a3 = 0.f;
    #pragma unroll
    for (int j = 0; j < 16; j++) {
        const float4 wv = *(const float4*)sW[wip][j];   // broadcast LDS.128
        const int4   iv = *(const int4*)  sI[wip][j];   // broadcast LDS.128
        a0 = fmaf(wv.x, __ldg(vp + iv.x), a0);
        a1 = fmaf(wv.y, __ldg(vp + iv.y), a1);
        a2 = fmaf(wv.z, __ldg(vp + iv.z), a2);
        a3 = fmaf(wv.w, __ldg(vp + iv.w), a3);
    }
    outpre[nq * 256 + h * 32 + lane] = (a0 + a1) + (a2 + a3);
}

// ---------------------------------------------------------------------------
extern "C" void kernel_launch(void* const* d_in, const int* in_sizes, int n_in,
                              void* d_out, int out_size)
{
    (void)in_sizes; (void)n_in; (void)out_size;
    const float* q      = (const float*)d_in[0];
    const float* p      = (const float*)d_in[1];
    const float* v      = (const float*)d_in[2];
    const float* W_off  = (const float*)d_in[3];
    const float* b_off  = (const float*)d_in[4];
    const float* W_attn = (const float*)d_in[5];
    const float* b_attn = (const float*)d_in[6];
    const float* W_in   = (const float*)d_in[7];
    const float* b_in   = (const float*)d_in[8];
    const float* W_out  = (const float*)d_in[9];
    const float* b_out  = (const float*)d_in[10];
    float* out = (float*)d_out;

    static float *vproj = nullptr, *offb = nullptr, *attnb = nullptr, *outpre = nullptr;
    if (!vproj) {
        cudaGetSymbolAddress((void**)&vproj,  g_vproj);
        cudaGetSymbolAddress((void**)&offb,   g_off);
        cudaGetSymbolAddress((void**)&attnb,  g_attn);
        cudaGetSymbolAddress((void**)&outpre, g_outpre);
    }

    dim3 blk(256);
    dim3 g256((NQ + BM - 1) / BM, 256 / BN);   // (192, 2)
    dim3 g128((NQ + BM - 1) / BM, 128 / BN);   // (192, 1)

    gemm_tf32_kernel<<<g256, blk>>>(v,      W_in,   b_in,   vproj,  NQ, 256);
    gemm_tf32_kernel<<<g256, blk>>>(q,      W_off,  b_off,  offb,   NQ, 256);
    gemm_tf32_kernel<<<g128, blk>>>(q,      W_attn, b_attn, attnb,  NQ, 128);
    sample_kernel<<<NQ, 256>>>(p, outpre);
    gemm_tf32_kernel<<<g256, blk>>>(outpre, W_out,  b_out,  out,    NQ, 256);
}

// round 7
// speedup vs baseline: 1.0198x; 1.0014x over previous
#include <cuda_runtime.h>
#include <math.h>

#define QQ   12240
#define NB   2
#define NQ   (NB*QQ)       // 24480
#define KD   256

// ---- scratch (static device globals; allocation is forbidden) ----
__device__ float g_vproj [NQ * 256];
__device__ float g_off   [NQ * 256];
__device__ float g_attn  [NQ * 128];
__device__ float g_outpre[NQ * 256];

// ---------------------------------------------------------------------------
// TF32 tensor-core GEMM: C[M,N] = A[M,256] @ W[256,N] + bias[N]
// BM=128, BN=128, BK=16, 256 threads (8 warps, 64x32 warp tiles),
// double-buffered smem, mma.sync.m16n8k8.tf32, fp32 accumulate.
// ---------------------------------------------------------------------------
#define BM 128
#define BN 128
#define BK 16
#define SA 136   // smem row stride (words): LDS banks (8k+m)%32 all distinct

__device__ __forceinline__ unsigned f2tf(float x) {
    unsigned r; asm("cvt.rna.tf32.f32 %0, %1;" : "=r"(r) : "f"(x)); return r;
}

__device__ __forceinline__ void mma_tf32(float* c, const unsigned* a, const unsigned* b) {
    asm volatile(
        "mma.sync.aligned.m16n8k8.row.col.f32.tf32.tf32.f32 "
        "{%0,%1,%2,%3}, {%4,%5,%6,%7}, {%8,%9}, {%0,%1,%2,%3};"
        : "+f"(c[0]), "+f"(c[1]), "+f"(c[2]), "+f"(c[3])
        : "r"(a[0]), "r"(a[1]), "r"(a[2]), "r"(a[3]), "r"(b[0]), "r"(b[1]));
}

__global__ __launch_bounds__(256) void gemm_tf32_kernel(
    const float* __restrict__ A,
    const float* __restrict__ W,
    const float* __restrict__ bias,
    float* __restrict__ C,
    int M, int N)
{
    __shared__ float As[2][BK][SA];   // As[buf][k][m]  (tf32 bit patterns)
    __shared__ float Bs[2][BK][SA];   // Bs[buf][k][n]

    const int tid  = threadIdx.x;
    const int lane = tid & 31;
    const int warp = tid >> 5;
    const int bm = blockIdx.x * BM;
    const int bn = blockIdx.y * BN;
    const int wm = (warp >> 2) << 6;   // 0 or 64
    const int wn = (warp & 3) << 5;    // 0,32,64,96

    const int ar = tid >> 1;             // 0..127
    const int ac = (tid & 1) << 3;       // 0 or 8
    const bool aval = (bm + ar) < M;
    const float* Ap = A + (size_t)(bm + ar) * KD + ac;

    const int br = tid >> 4;             // 0..15
    const int bc = (tid & 15) << 3;      // 0..120
    const float* Wp = W + (size_t)br * N + bn + bc;

    const int fr = lane >> 2;            // fragment row group 0..7
    const int fk = lane & 3;             // fragment k 0..3

    float acc[4][4][4];
    #pragma unroll
    for (int i = 0; i < 4; i++)
        #pragma unroll
        for (int j = 0; j < 4; j++)
            #pragma unroll
            for (int c = 0; c < 4; c++) acc[i][j][c] = 0.f;

    float4 av0, av1, bv0, bv1;
    if (aval) { av0 = *(const float4*)Ap; av1 = *(const float4*)(Ap + 4); }
    else      { av0 = make_float4(0,0,0,0); av1 = av0; }
    bv0 = *(const float4*)Wp;
    bv1 = *(const float4*)(Wp + 4);

    As[0][ac+0][ar] = __uint_as_float(f2tf(av0.x));
    As[0][ac+1][ar] = __uint_as_float(f2tf(av0.y));
    As[0][ac+2][ar] = __uint_as_float(f2tf(av0.z));
    As[0][ac+3][ar] = __uint_as_float(f2tf(av0.w));
    As[0][ac+4][ar] = __uint_as_float(f2tf(av1.x));
    As[0][ac+5][ar] = __uint_as_float(f2tf(av1.y));
    As[0][ac+6][ar] = __uint_as_float(f2tf(av1.z));
    As[0][ac+7][ar] = __uint_as_float(f2tf(av1.w));
    {
        float4 t0 = make_float4(__uint_as_float(f2tf(bv0.x)), __uint_as_float(f2tf(bv0.y)),
                                __uint_as_float(f2tf(bv0.z)), __uint_as_float(f2tf(bv0.w)));
        float4 t1 = make_float4(__uint_as_float(f2tf(bv1.x)), __uint_as_float(f2tf(bv1.y)),
                                __uint_as_float(f2tf(bv1.z)), __uint_as_float(f2tf(bv1.w)));
        *(float4*)&Bs[0][br][bc]     = t0;
        *(float4*)&Bs[0][br][bc + 4] = t1;
    }
    __syncthreads();

    const int NIT = KD / BK;   // 16
    for (int iter = 0; iter < NIT; iter++) {
        const int buf = iter & 1;

        if (iter + 1 < NIT) {
            const float* Ap2 = Ap + (iter + 1) * BK;
            if (aval) { av0 = *(const float4*)Ap2; av1 = *(const float4*)(Ap2 + 4); }
            const float* Wp2 = Wp + (size_t)(iter + 1) * BK * N;
            bv0 = *(const float4*)Wp2;
            bv1 = *(const float4*)(Wp2 + 4);
        }

        #pragma unroll
        for (int kk = 0; kk < BK; kk += 8) {
            unsigned af[4][4], bf[4][2];
            const int k0 = kk + fk;
            #pragma unroll
            for (int mt = 0; mt < 4; mt++) {
                const int m = wm + (mt << 4) + fr;
                af[mt][0] = __float_as_uint(As[buf][k0    ][m    ]);
                af[mt][1] = __float_as_uint(As[buf][k0    ][m + 8]);
                af[mt][2] = __float_as_uint(As[buf][k0 + 4][m    ]);
                af[mt][3] = __float_as_uint(As[buf][k0 + 4][m + 8]);
            }
            #pragma unroll
            for (int nt = 0; nt < 4; nt++) {
                const int nn = wn + (nt << 3) + fr;
                bf[nt][0] = __float_as_uint(Bs[buf][k0    ][nn]);
                bf[nt][1] = __float_as_uint(Bs[buf][k0 + 4][nn]);
            }
            #pragma unroll
            for (int mt = 0; mt < 4; mt++)
                #pragma unroll
                for (int nt = 0; nt < 4; nt++)
                    mma_tf32(acc[mt][nt], af[mt], bf[nt]);
        }

        if (iter + 1 < NIT) {
            const int nb = buf ^ 1;
            As[nb][ac+0][ar] = __uint_as_float(f2tf(av0.x));
            As[nb][ac+1][ar] = __uint_as_float(f2tf(av0.y));
            As[nb][ac+2][ar] = __uint_as_float(f2tf(av0.z));
            As[nb][ac+3][ar] = __uint_as_float(f2tf(av0.w));
            As[nb][ac+4][ar] = __uint_as_float(f2tf(av1.x));
            As[nb][ac+5][ar] = __uint_as_float(f2tf(av1.y));
            As[nb][ac+6][ar] = __uint_as_float(f2tf(av1.z));
            As[nb][ac+7][ar] = __uint_as_float(f2tf(av1.w));
            float4 t0 = make_float4(__uint_as_float(f2tf(bv0.x)), __uint_as_float(f2tf(bv0.y)),
                                    __uint_as_float(f2tf(bv0.z)), __uint_as_float(f2tf(bv0.w)));
            float4 t1 = make_float4(__uint_as_float(f2tf(bv1.x)), __uint_as_float(f2tf(bv1.y)),
                                    __uint_as_float(f2tf(bv1.z)), __uint_as_float(f2tf(bv1.w)));
            *(float4*)&Bs[nb][br][bc]     = t0;
            *(float4*)&Bs[nb][br][bc + 4] = t1;
            __syncthreads();
        }
    }

    #pragma unroll
    for (int nt = 0; nt < 4; nt++) {
        const int cc = bn + wn + (nt << 3) + ((lane & 3) << 1);
        const float2 bv = *(const float2*)(bias + cc);
        #pragma unroll
        for (int mt = 0; mt < 4; mt++) {
            const int r0 = bm + wm + (mt << 4) + (lane >> 2);
            if (r0 < M) {
                float2 o = make_float2(acc[mt][nt][0] + bv.x, acc[mt][nt][1] + bv.y);
                *(float2*)(C + (size_t)r0 * N + cc) = o;
            }
            if (r0 + 8 < M) {
                float2 o = make_float2(acc[mt][nt][2] + bv.x, acc[mt][nt][3] + bv.y);
                *(float2*)(C + (size_t)(r0 + 8) * N + cc) = o;
            }
        }
    }
}

// ---------------------------------------------------------------------------
// Deformable sampling. One warp per (n, q, head); lane == channel (CH=32).
// Phase A: lane j<16 computes point j's 4 pre-masked weights (x softmax) and
//          4 pre-scaled clamped indices; writes them to smem (2x STS.128).
// Phase B: per point, 2 broadcast LDS.128 + 4 coalesced LDG + 4 FMA.
// ---------------------------------------------------------------------------
__global__ __launch_bounds__(256) void sample_kernel(
    const float* __restrict__ pref,
    float* __restrict__ outpre)
{
    __shared__ float sW[8][16][4];   // per warp, per point: W00,W10,W01,W11
    __shared__ int   sI[8][16][4];   // i00,i10,i01,i11 (pre-scaled by 256)

    const unsigned FULL = 0xffffffffu;
    const int lane = threadIdx.x & 31;
    const int wip  = threadIdx.x >> 5;
    const int warp = (blockIdx.x << 3) + wip;
    const int h    = warp & 7;
    const int nq   = warp >> 3;
    const int n    = (nq >= QQ) ? 1 : 0;

    const int jj = lane & 15;
    const int l  = jj >> 2;
    const int Wl = 96 >> l;
    const float fw = (float)Wl;
    const int sb = (l == 0) ? 0 : (l == 1) ? 9216 : (l == 2) ? 11520 : 12096;

    // ---- softmax over this head's 16 logits (dup across warp halves) ----
    float logit = g_attn[nq * 128 + h * 16 + jj];
    float mx = logit;
    #pragma unroll
    for (int o = 8; o >= 1; o >>= 1)
        mx = fmaxf(mx, __shfl_xor_sync(FULL, mx, o));
    float e = __expf(logit - mx);
    float s = e;
    #pragma unroll
    for (int o = 8; o >= 1; o >>= 1)
        s += __shfl_xor_sync(FULL, s, o);
    const float aw = e / s;

    // ---- point jj: coords / masked weights / clamped indices ----
    const float2 o2 = ((const float2*)(g_off + nq * 256 + h * 32))[jj];
    const float2 pr = ((const float2*)(pref + nq * 8))[l];
    const float x = fmaf(pr.x, fw, o2.x) - 0.5f;   // == (p + off/W)*W - 0.5
    const float y = fmaf(pr.y, fw, o2.y) - 0.5f;
    const float x0f = floorf(x), y0f = floorf(y);
    const float dx = x - x0f, dy = y - y0f;
    const int x0 = (int)x0f, y0 = (int)y0f;
    const int x1 = x0 + 1,   y1 = y0 + 1;
    const bool vx0 = (unsigned)x0 < (unsigned)Wl;
    const bool vx1 = (unsigned)x1 < (unsigned)Wl;
    const bool vy0 = (unsigned)y0 < (unsigned)Wl;
    const bool vy1 = (unsigned)y1 < (unsigned)Wl;
    const int x0c = min(max(x0, 0), Wl - 1);
    const int x1c = min(max(x1, 0), Wl - 1);
    const int y0c = min(max(y0, 0), Wl - 1);
    const int y1c = min(max(y1, 0), Wl - 1);
    const float ex = 1.f - dx, ey = 1.f - dy;
    const float u0 = aw * ex, u1 = aw * dx;

    if (lane < 16) {
        float4 wv;
        wv.x = (vx0 & vy0) ? u0 * ey : 0.f;
        wv.y = (vx1 & vy0) ? u1 * ey : 0.f;
        wv.z = (vx0 & vy1) ? u0 * dy : 0.f;
        wv.w = (vx1 & vy1) ? u1 * dy : 0.f;
        const int r0 = sb + y0c * Wl;
        const int r1 = sb + y1c * Wl;
        int4 iv;
        iv.x = (r0 + x0c) << 8;
        iv.y = (r0 + x1c) << 8;
        iv.z = (r1 + x0c) << 8;
        iv.w = (r1 + x1c) << 8;
        *(float4*)sW[wip][jj] = wv;
        *(int4*)  sI[wip][jj] = iv;
    }
    __syncwarp();

    // ---- gather & accumulate ----
    const float* vp = g_vproj + (size_t)n * (QQ * 256) + h * 32 + lane;
    float a0 = 0.f, a1 = 0.f, a2 = 0.f, a3 = 0.f;
    #pragma unroll
    for (int j = 0; j < 16; j++) {
        const float4 wv = *(const float4*)sW[wip][j];   // broadcast LDS.128
        const int4   iv = *(const int4*)  sI[wip][j];   // broadcast LDS.128
        a0 = fmaf(wv.x, __ldg(vp + iv.x), a0);
        a1 = fmaf(wv.y, __ldg(vp + iv.y), a1);
        a2 = fmaf(wv.z, __ldg(vp + iv.z), a2);
        a3 = fmaf(wv.w, __ldg(vp + iv.w), a3);
    }
    outpre[nq * 256 + h * 32 + lane] = (a0 + a1) + (a2 + a3);
}

// ---------------------------------------------------------------------------
extern "C" void kernel_launch(void* const* d_in, const int* in_sizes, int n_in,
                              void* d_out, int out_size)
{
    (void)in_sizes; (void)n_in; (void)out_size;
    const float* q      = (const float*)d_in[0];
    const float* p      = (const float*)d_in[1];
    const float* v      = (const float*)d_in[2];
    const float* W_off  = (const float*)d_in[3];
    const float* b_off  = (const float*)d_in[4];
    const float* W_attn = (const float*)d_in[5];
    const float* b_attn = (const float*)d_in[6];
    const float* W_in   = (const float*)d_in[7];
    const float* b_in   = (const float*)d_in[8];
    const float* W_out  = (const float*)d_in[9];
    const float* b_out  = (const float*)d_in[10];
    float* out = (float*)d_out;

    static float *vproj = nullptr, *offb = nullptr, *attnb = nullptr, *outpre = nullptr;
    if (!vproj) {
        cudaGetSymbolAddress((void**)&vproj,  g_vproj);
        cudaGetSymbolAddress((void**)&offb,   g_off);
        cudaGetSymbolAddress((void**)&attnb,  g_attn);
        cudaGetSymbolAddress((void**)&outpre, g_outpre);
    }

    dim3 blk(256);
    dim3 g256((NQ + BM - 1) / BM, 256 / BN);   // (192, 2)
    dim3 g128((NQ + BM - 1) / BM, 128 / BN);   // (192, 1)

    gemm_tf32_kernel<<<g256, blk>>>(v,      W_in,   b_in,   vproj,  NQ, 256);
    gemm_tf32_kernel<<<g256, blk>>>(q,      W_off,  b_off,  offb,   NQ, 256);
    gemm_tf32_kernel<<<g128, blk>>>(q,      W_attn, b_attn, attnb,  NQ, 128);
    sample_kernel<<<NQ, 256>>>(p, outpre);
    gemm_tf32_kernel<<<g256, blk>>>(outpre, W_out,  b_out,  out,    NQ, 256);
}

// round 8
// speedup vs baseline: 1.0208x; 1.0009x over previous
#include <cuda_runtime.h>
#include <math.h>

#define QQ   12240
#define NB   2
#define NQ   (NB*QQ)       // 24480
#define KD   256

// ---- scratch (static device globals; allocation is forbidden) ----
__device__ float g_vproj [NQ * 256];
__device__ float g_off   [NQ * 256];
__device__ float g_attn  [NQ * 128];
__device__ float g_outpre[NQ * 256];

// ---------------------------------------------------------------------------
// TF32 tensor-core GEMM: C[M,N] = A[M,256] @ W[256,N] + bias[N]
// BM=128, BN=128, BK=16, 256 threads (8 warps, 64x32 warp tiles),
// double-buffered smem, mma.sync.m16n8k8.tf32, fp32 accumulate.
// ---------------------------------------------------------------------------
#define BM 128
#define BN 128
#define BK 16
#define SA 136   // smem row stride (words): LDS banks (8k+m)%32 all distinct

__device__ __forceinline__ unsigned f2tf(float x) {
    unsigned r; asm("cvt.rna.tf32.f32 %0, %1;" : "=r"(r) : "f"(x)); return r;
}

__device__ __forceinline__ void mma_tf32(float* c, const unsigned* a, const unsigned* b) {
    asm volatile(
        "mma.sync.aligned.m16n8k8.row.col.f32.tf32.tf32.f32 "
        "{%0,%1,%2,%3}, {%4,%5,%6,%7}, {%8,%9}, {%0,%1,%2,%3};"
        : "+f"(c[0]), "+f"(c[1]), "+f"(c[2]), "+f"(c[3])
        : "r"(a[0]), "r"(a[1]), "r"(a[2]), "r"(a[3]), "r"(b[0]), "r"(b[1]));
}

__global__ __launch_bounds__(256) void gemm_tf32_kernel(
    const float* __restrict__ A,
    const float* __restrict__ W,
    const float* __restrict__ bias,
    float* __restrict__ C,
    int M, int N)
{
    __shared__ float As[2][BK][SA];   // As[buf][k][m]  (tf32 bit patterns)
    __shared__ float Bs[2][BK][SA];   // Bs[buf][k][n]

    const int tid  = threadIdx.x;
    const int lane = tid & 31;
    const int warp = tid >> 5;
    const int bm = blockIdx.x * BM;
    const int bn = blockIdx.y * BN;
    const int wm = (warp >> 2) << 6;   // 0 or 64
    const int wn = (warp & 3) << 5;    // 0,32,64,96

    const int ar = tid >> 1;             // 0..127
    const int ac = (tid & 1) << 3;       // 0 or 8
    const bool aval = (bm + ar) < M;
    const float* Ap = A + (size_t)(bm + ar) * KD + ac;

    const int br = tid >> 4;             // 0..15
    const int bc = (tid & 15) << 3;      // 0..120
    const float* Wp = W + (size_t)br * N + bn + bc;

    const int fr = lane >> 2;            // fragment row group 0..7
    const int fk = lane & 3;             // fragment k 0..3

    float acc[4][4][4];
    #pragma unroll
    for (int i = 0; i < 4; i++)
        #pragma unroll
        for (int j = 0; j < 4; j++)
            #pragma unroll
            for (int c = 0; c < 4; c++) acc[i][j][c] = 0.f;

    float4 av0, av1, bv0, bv1;
    if (aval) { av0 = *(const float4*)Ap; av1 = *(const float4*)(Ap + 4); }
    else      { av0 = make_float4(0,0,0,0); av1 = av0; }
    bv0 = *(const float4*)Wp;
    bv1 = *(const float4*)(Wp + 4);

    As[0][ac+0][ar] = __uint_as_float(f2tf(av0.x));
    As[0][ac+1][ar] = __uint_as_float(f2tf(av0.y));
    As[0][ac+2][ar] = __uint_as_float(f2tf(av0.z));
    As[0][ac+3][ar] = __uint_as_float(f2tf(av0.w));
    As[0][ac+4][ar] = __uint_as_float(f2tf(av1.x));
    As[0][ac+5][ar] = __uint_as_float(f2tf(av1.y));
    As[0][ac+6][ar] = __uint_as_float(f2tf(av1.z));
    As[0][ac+7][ar] = __uint_as_float(f2tf(av1.w));
    {
        float4 t0 = make_float4(__uint_as_float(f2tf(bv0.x)), __uint_as_float(f2tf(bv0.y)),
                                __uint_as_float(f2tf(bv0.z)), __uint_as_float(f2tf(bv0.w)));
        float4 t1 = make_float4(__uint_as_float(f2tf(bv1.x)), __uint_as_float(f2tf(bv1.y)),
                                __uint_as_float(f2tf(bv1.z)), __uint_as_float(f2tf(bv1.w)));
        *(float4*)&Bs[0][br][bc]     = t0;
        *(float4*)&Bs[0][br][bc + 4] = t1;
    }
    __syncthreads();

    const int NIT = KD / BK;   // 16
    for (int iter = 0; iter < NIT; iter++) {
        const int buf = iter & 1;

        if (iter + 1 < NIT) {
            const float* Ap2 = Ap + (iter + 1) * BK;
            if (aval) { av0 = *(const float4*)Ap2; av1 = *(const float4*)(Ap2 + 4); }
            const float* Wp2 = Wp + (size_t)(iter + 1) * BK * N;
            bv0 = *(const float4*)Wp2;
            bv1 = *(const float4*)(Wp2 + 4);
        }

        #pragma unroll
        for (int kk = 0; kk < BK; kk += 8) {
            unsigned af[4][4], bf[4][2];
            const int k0 = kk + fk;
            #pragma unroll
            for (int mt = 0; mt < 4; mt++) {
                const int m = wm + (mt << 4) + fr;
                af[mt][0] = __float_as_uint(As[buf][k0    ][m    ]);
                af[mt][1] = __float_as_uint(As[buf][k0    ][m + 8]);
                af[mt][2] = __float_as_uint(As[buf][k0 + 4][m    ]);
                af[mt][3] = __float_as_uint(As[buf][k0 + 4][m + 8]);
            }
            #pragma unroll
            for (int nt = 0; nt < 4; nt++) {
                const int nn = wn + (nt << 3) + fr;
                bf[nt][0] = __float_as_uint(Bs[buf][k0    ][nn]);
                bf[nt][1] = __float_as_uint(Bs[buf][k0 + 4][nn]);
            }
            #pragma unroll
            for (int mt = 0; mt < 4; mt++)
                #pragma unroll
                for (int nt = 0; nt < 4; nt++)
                    mma_tf32(acc[mt][nt], af[mt], bf[nt]);
        }

        if (iter + 1 < NIT) {
            const int nb = buf ^ 1;
            As[nb][ac+0][ar] = __uint_as_float(f2tf(av0.x));
            As[nb][ac+1][ar] = __uint_as_float(f2tf(av0.y));
            As[nb][ac+2][ar] = __uint_as_float(f2tf(av0.z));
            As[nb][ac+3][ar] = __uint_as_float(f2tf(av0.w));
            As[nb][ac+4][ar] = __uint_as_float(f2tf(av1.x));
            As[nb][ac+5][ar] = __uint_as_float(f2tf(av1.y));
            As[nb][ac+6][ar] = __uint_as_float(f2tf(av1.z));
            As[nb][ac+7][ar] = __uint_as_float(f2tf(av1.w));
            float4 t0 = make_float4(__uint_as_float(f2tf(bv0.x)), __uint_as_float(f2tf(bv0.y)),
                                    __uint_as_float(f2tf(bv0.z)), __uint_as_float(f2tf(bv0.w)));
            float4 t1 = make_float4(__uint_as_float(f2tf(bv1.x)), __uint_as_float(f2tf(bv1.y)),
                                    __uint_as_float(f2tf(bv1.z)), __uint_as_float(f2tf(bv1.w)));
            *(float4*)&Bs[nb][br][bc]     = t0;
            *(float4*)&Bs[nb][br][bc + 4] = t1;
            __syncthreads();
        }
    }

    #pragma unroll
    for (int nt = 0; nt < 4; nt++) {
        const int cc = bn + wn + (nt << 3) + ((lane & 3) << 1);
        const float2 bv = *(const float2*)(bias + cc);
        #pragma unroll
        for (int mt = 0; mt < 4; mt++) {
            const int r0 = bm + wm + (mt << 4) + (lane >> 2);
            if (r0 < M) {
                float2 o = make_float2(acc[mt][nt][0] + bv.x, acc[mt][nt][1] + bv.y);
                *(float2*)(C + (size_t)r0 * N + cc) = o;
            }
            if (r0 + 8 < M) {
                float2 o = make_float2(acc[mt][nt][2] + bv.x, acc[mt][nt][3] + bv.y);
                *(float2*)(C + (size_t)(r0 + 8) * N + cc) = o;
            }
        }
    }
}

// ---------------------------------------------------------------------------
// Deformable sampling. One warp per (n, q, head); lane == channel (CH=32).
// Phase A: lane j<16 computes point j's 4 pre-masked weights (x softmax) and
//          4 pre-scaled clamped indices; writes them to smem (2x STS.128).
// Phase B: per point, 2 broadcast LDS.128 + 4 coalesced LDG + 4 FMA.
// ---------------------------------------------------------------------------
__global__ __launch_bounds__(256) void sample_kernel(
    const float* __restrict__ pref,
    float* __restrict__ outpre)
{
    __shared__ float sW[8][16][4];   // per warp, per point: W00,W10,W01,W11
    __shared__ int   sI[8][16][4];   // i00,i10,i01,i11 (pre-scaled by 256)

    const unsigned FULL = 0xffffffffu;
    const int lane = threadIdx.x & 31;
    const int wip  = threadIdx.x >> 5;
    const int warp = (blockIdx.x << 3) + wip;
    const int h    = warp & 7;
    const int nq   = warp >> 3;
    const int n    = (nq >= QQ) ? 1 : 0;

    const int jj = lane & 15;
    const int l  = jj >> 2;
    const int Wl = 96 >> l;
    const float fw = (float)Wl;
    const int sb = (l == 0) ? 0 : (l == 1) ? 9216 : (l == 2) ? 11520 : 12096;

    // ---- softmax over this head's 16 logits (dup across warp halves) ----
    float logit = g_attn[nq * 128 + h * 16 + jj];
    float mx = logit;
    #pragma unroll
    for (int o = 8; o >= 1; o >>= 1)
        mx = fmaxf(mx, __shfl_xor_sync(FULL, mx, o));
    float e = __expf(logit - mx);
    float s = e;
    #pragma unroll
    for (int o = 8; o >= 1; o >>= 1)
        s += __shfl_xor_sync(FULL, s, o);
    const float aw = e / s;

    // ---- point jj: coords / masked weights / clamped indices ----
    const float2 o2 = ((const float2*)(g_off + nq * 256 + h * 32))[jj];
    const float2 pr = ((const float2*)(pref + nq * 8))[l];
    const float x = fmaf(pr.x, fw, o2.x) - 0.5f;   // == (p + off/W)*W - 0.5
    const float y = fmaf(pr.y, fw, o2.y) - 0.5f;
    const float x0f = floorf(x), y0f = floorf(y);
    const float dx = x - x0f, dy = y - y0f;
    const int x0 = (int)x0f, y0 = (int)y0f;
    const int x1 = x0 + 1,   y1 = y0 + 1;
    const bool vx0 = (unsigned)x0 < (unsigned)Wl;
    const bool vx1 = (unsigned)x1 < (unsigned)Wl;
    const bool vy0 = (unsigned)y0 < (unsigned)Wl;
    const bool vy1 = (unsigned)y1 < (unsigned)Wl;
    const int x0c = min(max(x0, 0), Wl - 1);
    const int x1c = min(max(x1, 0), Wl - 1);
    const int y0c = min(max(y0, 0), Wl - 1);
    const int y1c = min(max(y1, 0), Wl - 1);
    const float ex = 1.f - dx, ey = 1.f - dy;
    const float u0 = aw * ex, u1 = aw * dx;

    if (lane < 16) {
        float4 wv;
        wv.x = (vx0 & vy0) ? u0 * ey : 0.f;
        wv.y = (vx1 & vy0) ? u1 * ey : 0.f;
        wv.z = (vx0 & vy1) ? u0 * dy : 0.f;
        wv.w = (vx1 & vy1) ? u1 * dy : 0.f;
        const int r0 = sb + y0c * Wl;
        const int r1 = sb + y1c * Wl;
        int4 iv;
        iv.x = (r0 + x0c) << 8;
        iv.y = (r0 + x1c) << 8;
        iv.z = (r1 + x0c) << 8;
        iv.w = (r1 + x1c) << 8;
        *(float4*)sW[wip][jj] = wv;
        *(int4*)  sI[wip][jj] = iv;
    }
    __syncwarp();

    // ---- gather & accumulate ----
    const float* vp = g_vproj + (size_t)n * (QQ * 256) + h * 32 + lane;
    float a0 = 0.f, a1 = 0.f, a2 = 0.f, a3 = 0.f;
    #pragma unroll
    for (int j = 0; j < 16; j++) {
        const float4 wv = *(const float4*)sW[wip][j];   // broadcast LDS.128
        const int4   iv = *(const int4*)  sI[wip][j];   // broadcast LDS.128
        a0 = fmaf(wv.x, __ldg(vp + iv.x), a0);
        a1 = fmaf(wv.y, __ldg(vp + iv.y), a1);
        a2 = fmaf(wv.z, __ldg(vp + iv.z), a2);
        a3 = fmaf(wv.w, __ldg(vp + iv.w), a3);
    }
    outpre[nq * 256 + h * 32 + lane] = (a0 + a1) + (a2 + a3);
}

// ---------------------------------------------------------------------------
extern "C" void kernel_launch(void* const* d_in, const int* in_sizes, int n_in,
                              void* d_out, int out_size)
{
    (void)in_sizes; (void)n_in; (void)out_size;
    const float* q      = (const float*)d_in[0];
    const float* p      = (const float*)d_in[1];
    const float* v      = (const float*)d_in[2];
    const float* W_off  = (const float*)d_in[3];
    const float* b_off  = (const float*)d_in[4];
    const float* W_attn = (const float*)d_in[5];
    const float* b_attn = (const float*)d_in[6];
    const float* W_in   = (const float*)d_in[7];
    const float* b_in   = (const float*)d_in[8];
    const float* W_out  = (const float*)d_in[9];
    const float* b_out  = (const float*)d_in[10];
    float* out = (float*)d_out;

    static float *vproj = nullptr, *offb = nullptr, *attnb = nullptr, *outpre = nullptr;
    if (!vproj) {
        cudaGetSymbolAddress((void**)&vproj,  g_vproj);
        cudaGetSymbolAddress((void**)&offb,   g_off);
        cudaGetSymbolAddress((void**)&attnb,  g_attn);
        cudaGetSymbolAddress((void**)&outpre, g_outpre);
    }

    dim3 blk(256);
    dim3 g256((NQ + BM - 1) / BM, 256 / BN);   // (192, 2)
    dim3 g128((NQ + BM - 1) / BM, 128 / BN);   // (192, 1)

    gemm_tf32_kernel<<<g256, blk>>>(v,      W_in,   b_in,   vproj,  NQ, 256);
    gemm_tf32_kernel<<<g256, blk>>>(q,      W_off,  b_off,  offb,   NQ, 256);
    gemm_tf32_kernel<<<g128, blk>>>(q,      W_attn, b_attn, attnb,  NQ, 128);
    sample_kernel<<<NQ, 256>>>(p, outpre);
    gemm_tf32_kernel<<<g256, blk>>>(outpre, W_out,  b_out,  out,    NQ, 256);
}